// round 12
// baseline (speedup 1.0000x reference)
#include <cuda_runtime.h>
#include <cuda_bf16.h>
#include <cuda_fp16.h>
#include <cstdint>

#define NN 50000
#define NE 1600000
#define IN_F 256
#define OUT_C 128   // H*F
#define NH 4
#define NEG 0.2f

// scratch (allocation-free rule: __device__ globals)
__device__ __align__(16) float  g_h[NN * OUT_C];     // projected features fp32 [N,128]
__device__ __align__(16) __half g_hh[NN * OUT_C];    // fp16 copy for gather   [N,128]
__device__ __align__(16) float  g_el[NN * NH];       // left logits  [N,4]
__device__ __align__(16) float  g_er[NN * NH];       // right logits [N,4]
__device__ int g_cnt[NN];                            // in-degree histogram
__device__ int g_off[NN + 1];                        // CSR offsets (by dst)
__device__ __align__(16) int g_rank[NE];             // edge rank within its dst
__device__ int g_csr_src[NE];                        // src node per CSR slot

// ---------------------------------------------------------------------------
// CSR build: zero -> hist(+rank) -> scan -> scatter (atomic-free scatter)
// NE % 8 == 0: one guard per thread, int4-vectorized edge loads.
// ---------------------------------------------------------------------------
__global__ void zero_cnt_kernel() {
    int i = blockIdx.x * blockDim.x + threadIdx.x;
    if (i < NN) g_cnt[i] = 0;
}

__global__ void hist_kernel(const int* __restrict__ dst) {
    int base = (blockIdx.x * blockDim.x + threadIdx.x) * 8;
    if (base >= NE) return;
    int4 d0 = *(const int4*)(dst + base);
    int4 d1 = *(const int4*)(dst + base + 4);
    int d[8] = {d0.x, d0.y, d0.z, d0.w, d1.x, d1.y, d1.z, d1.w};
    int r[8];
#pragma unroll
    for (int j = 0; j < 8; j++) r[j] = atomicAdd(&g_cnt[d[j]], 1);
    *(int4*)(g_rank + base)     = make_int4(r[0], r[1], r[2], r[3]);
    *(int4*)(g_rank + base + 4) = make_int4(r[4], r[5], r[6], r[7]);
}

__global__ __launch_bounds__(1024) void scan_kernel() {
    __shared__ int ssum[1024];
    const int CH = (NN + 1023) / 1024;  // 49
    int t = threadIdx.x;
    int b = t * CH;
    int e = min(b + CH, NN);
    int s = 0;
    for (int i = b; i < e; i++) s += g_cnt[i];
    ssum[t] = s;
    __syncthreads();
    for (int off = 1; off < 1024; off <<= 1) {
        int v = (t >= off) ? ssum[t - off] : 0;
        __syncthreads();
        ssum[t] += v;
        __syncthreads();
    }
    int run = ssum[t] - s;
    for (int i = b; i < e; i++) {
        int c = g_cnt[i];
        g_off[i] = run;
        run += c;
    }
    if (t == 1023) g_off[NN] = NE;
}

__global__ void scatter_kernel(const int* __restrict__ src, const int* __restrict__ dst) {
    int base = (blockIdx.x * blockDim.x + threadIdx.x) * 8;
    if (base >= NE) return;
    int4 d0 = *(const int4*)(dst + base);
    int4 d1 = *(const int4*)(dst + base + 4);
    int4 s0 = *(const int4*)(src + base);
    int4 s1 = *(const int4*)(src + base + 4);
    int4 r0 = *(const int4*)(g_rank + base);
    int4 r1 = *(const int4*)(g_rank + base + 4);
    int d[8] = {d0.x, d0.y, d0.z, d0.w, d1.x, d1.y, d1.z, d1.w};
    int s[8] = {s0.x, s0.y, s0.z, s0.w, s1.x, s1.y, s1.z, s1.w};
    int r[8] = {r0.x, r0.y, r0.z, r0.w, r1.x, r1.y, r1.z, r1.w};
    int o[8];
#pragma unroll
    for (int j = 0; j < 8; j++) o[j] = g_off[d[j]];
#pragma unroll
    for (int j = 0; j < 8; j++) g_csr_src[o[j] + r[j]] = s[j];
}

// ---------------------------------------------------------------------------
// Projection: h = feat @ W^T via bf16-split tensor-core GEMM.
// ---------------------------------------------------------------------------
#define SPIT 40

__device__ __forceinline__ void bsplit(float x, __nv_bfloat16& hi, __nv_bfloat16& lo) {
    hi = __float2bfloat16_rn(x);
    lo = __float2bfloat16_rn(x - __bfloat162float(hi));
}

__device__ __forceinline__ void ldm_x4(unsigned* r, const __nv_bfloat16* p) {
    unsigned a = (unsigned)__cvta_generic_to_shared(p);
    asm volatile("ldmatrix.sync.aligned.m8n8.x4.shared.b16 {%0,%1,%2,%3}, [%4];"
                 : "=r"(r[0]), "=r"(r[1]), "=r"(r[2]), "=r"(r[3]) : "r"(a));
}

__device__ __forceinline__ void mma16816(float* c, const unsigned* a,
                                         unsigned b0, unsigned b1) {
    asm volatile("mma.sync.aligned.m16n8k16.row.col.f32.bf16.bf16.f32 "
                 "{%0,%1,%2,%3},{%4,%5,%6,%7},{%8,%9},{%0,%1,%2,%3};"
                 : "+f"(c[0]), "+f"(c[1]), "+f"(c[2]), "+f"(c[3])
                 : "r"(a[0]), "r"(a[1]), "r"(a[2]), "r"(a[3]), "r"(b0), "r"(b1));
}

__global__ __launch_bounds__(256) void proj_mma_kernel(
    const float* __restrict__ feat, const float* __restrict__ W)
{
    __shared__ __nv_bfloat16 sAhi[128][SPIT];
    __shared__ __nv_bfloat16 sAlo[128][SPIT];
    __shared__ __nv_bfloat16 sBhi[128][SPIT];
    __shared__ __nv_bfloat16 sBlo[128][SPIT];

    int t = threadIdx.x;
    int lane = t & 31;
    int wid = t >> 5;
    int wm = wid & 3;
    int wn = wid >> 2;
    int node0 = blockIdx.x * 128;

    float acc[2][8][4];
#pragma unroll
    for (int i = 0; i < 2; i++)
#pragma unroll
        for (int j = 0; j < 8; j++)
#pragma unroll
            for (int q = 0; q < 4; q++) acc[i][j][q] = 0.0f;

    for (int k0 = 0; k0 < IN_F; k0 += 32) {
#pragma unroll
        for (int j = 0; j < 4; j++) {
            int id = t + j * 256;            // 0..1023
            int row = id >> 3;
            int c4 = (id & 7) * 4;
            int node = node0 + row;
            if (node >= NN) node = NN - 1;
            float4 v = *(const float4*)(feat + (long)node * IN_F + k0 + c4);
            bsplit(v.x, sAhi[row][c4 + 0], sAlo[row][c4 + 0]);
            bsplit(v.y, sAhi[row][c4 + 1], sAlo[row][c4 + 1]);
            bsplit(v.z, sAhi[row][c4 + 2], sAlo[row][c4 + 2]);
            bsplit(v.w, sAhi[row][c4 + 3], sAlo[row][c4 + 3]);
        }
#pragma unroll
        for (int j = 0; j < 4; j++) {
            int id = t + j * 256;
            int row = id >> 3;
            int c4 = (id & 7) * 4;
            float4 v = *(const float4*)(W + (long)row * IN_F + k0 + c4);
            bsplit(v.x, sBhi[row][c4 + 0], sBlo[row][c4 + 0]);
            bsplit(v.y, sBhi[row][c4 + 1], sBlo[row][c4 + 1]);
            bsplit(v.z, sBhi[row][c4 + 2], sBlo[row][c4 + 2]);
            bsplit(v.w, sBhi[row][c4 + 3], sBlo[row][c4 + 3]);
        }
        __syncthreads();

#pragma unroll
        for (int ks = 0; ks < 2; ks++) {
            int koff = ks * 16;
            unsigned ahi[2][4], alo[2][4];
#pragma unroll
            for (int mt = 0; mt < 2; mt++) {
                int row = wm * 32 + mt * 16 + (lane & 15);
                int col = koff + (lane >> 4) * 8;
                ldm_x4(ahi[mt], &sAhi[row][col]);
                ldm_x4(alo[mt], &sAlo[row][col]);
            }
            unsigned bhi[4][4], blo[4][4];
#pragma unroll
            for (int ng = 0; ng < 4; ng++) {
                int row = wn * 64 + ng * 16 + (lane & 7) + ((lane >> 4) << 3);
                int col = koff + ((lane >> 3) & 1) * 8;
                ldm_x4(bhi[ng], &sBhi[row][col]);
                ldm_x4(blo[ng], &sBlo[row][col]);
            }
#pragma unroll
            for (int mt = 0; mt < 2; mt++)
#pragma unroll
                for (int ng = 0; ng < 4; ng++)
#pragma unroll
                    for (int hf = 0; hf < 2; hf++) {
                        float* c = acc[mt][ng * 2 + hf];
                        mma16816(c, ahi[mt], bhi[ng][hf * 2], bhi[ng][hf * 2 + 1]);
                        mma16816(c, ahi[mt], blo[ng][hf * 2], blo[ng][hf * 2 + 1]);
                        mma16816(c, alo[mt], bhi[ng][hf * 2], bhi[ng][hf * 2 + 1]);
                    }
        }
        __syncthreads();
    }

    // epilogue: C fragment -> g_h (fp32) + g_hh (fp16)
    int grp = lane >> 2;
    int tg = lane & 3;
#pragma unroll
    for (int mt = 0; mt < 2; mt++) {
#pragma unroll
        for (int nt = 0; nt < 8; nt++) {
            int row = node0 + wm * 32 + mt * 16 + grp;
            int col = wn * 64 + nt * 8 + tg * 2;
            float* c = acc[mt][nt];
            if (row < NN) {
                *(float2*)(g_h + (long)row * OUT_C + col) = make_float2(c[0], c[1]);
                *(__half2*)(g_hh + (long)row * OUT_C + col) = __floats2half2_rn(c[0], c[1]);
            }
            if (row + 8 < NN) {
                *(float2*)(g_h + (long)(row + 8) * OUT_C + col) = make_float2(c[2], c[3]);
                *(__half2*)(g_hh + (long)(row + 8) * OUT_C + col) = __floats2half2_rn(c[2], c[3]);
            }
        }
    }
}

// ---------------------------------------------------------------------------
// el/er: per (node, head) dot of h row-chunk with attn vectors (L2-resident)
// ---------------------------------------------------------------------------
__global__ void elr_kernel(const float* __restrict__ al, const float* __restrict__ ar) {
    int i = blockIdx.x * blockDim.x + threadIdx.x;   // node*NH + head
    if (i >= NN * NH) return;
    int node = i >> 2;
    int head = i & 3;
    const float* hp = g_h + (long)node * OUT_C + head * 32;
    float sl = 0.f, sr = 0.f;
#pragma unroll
    for (int j = 0; j < 8; j++) {
        float4 v = *(const float4*)(hp + j * 4);
        float4 a = *(const float4*)(al + head * 32 + j * 4);
        float4 b = *(const float4*)(ar + head * 32 + j * 4);
        sl += v.x * a.x + v.y * a.y + v.z * a.z + v.w * a.w;
        sr += v.x * b.x + v.y * b.y + v.z * b.z + v.w * b.w;
    }
    g_el[i] = sl;
    g_er[i] = sr;
}

// ---------------------------------------------------------------------------
// Fused softmax + aggregation: single-phase, half-warp per edge,
// SOFTWARE-PIPELINED 2 deep: src indices prefetched 2 iterations ahead,
// (el, h) data prefetched 1 iteration ahead; compute runs on registers.
// Both L2 round trips overlap compute instead of serializing.
// ---------------------------------------------------------------------------
__global__ __launch_bounds__(256) void agg_kernel(const float* __restrict__ bias,
                                                  float* __restrict__ out)
{
    int wib  = threadIdx.x >> 5;
    int lane = threadIdx.x & 31;
    int node = blockIdx.x * 8 + wib;
    if (node >= NN) return;

    int beg = g_off[node];
    int end = g_off[node + 1];

    int half = lane >> 4;      // which edge of the pair
    int hl   = lane & 15;      // lane within half-warp
    int hd2  = hl >> 2;        // head for my column range

    const float erv = g_er[node * NH + hd2];

    float dsum = 0.f;
    float acc8[8];
#pragma unroll
    for (int k = 0; k < 8; k++) acc8[k] = 0.f;

    const long colo = (long)hl * 8;   // fp16 column offset for this lane
    const int eoff = half * 2;

    int nfull = (end - beg) >> 2;     // full 4-edge iterations

    // pipeline registers
    int sA1 = 0, sB1 = 0;                      // src for iter i+1
    float lA0 = 0.f, lB0 = 0.f;                // data for iter i
    uint4 hA0 = make_uint4(0, 0, 0, 0);
    uint4 hB0 = make_uint4(0, 0, 0, 0);

    if (nfull > 0) {
        int eb = beg + eoff;
        int sA0 = g_csr_src[eb];
        int sB0 = g_csr_src[eb + 1];
        if (nfull > 1) {
            int eb1 = beg + 4 + eoff;
            sA1 = g_csr_src[eb1];
            sB1 = g_csr_src[eb1 + 1];
        }
        lA0 = g_el[sA0 * NH + hd2];
        lB0 = g_el[sB0 * NH + hd2];
        hA0 = *(const uint4*)((const char*)g_hh + ((long)sA0 * OUT_C + colo) * 2);
        hB0 = *(const uint4*)((const char*)g_hh + ((long)sB0 * OUT_C + colo) * 2);
    }

    for (int i = 0; i < nfull; i++) {
        // prefetch src for iter i+2
        int sA2 = 0, sB2 = 0;
        if (i + 2 < nfull) {
            int eb = beg + (i + 2) * 4 + eoff;
            sA2 = g_csr_src[eb];
            sB2 = g_csr_src[eb + 1];
        }
        // prefetch data for iter i+1 (src already resident)
        float lA1 = 0.f, lB1 = 0.f;
        uint4 hA1 = make_uint4(0, 0, 0, 0);
        uint4 hB1 = make_uint4(0, 0, 0, 0);
        if (i + 1 < nfull) {
            lA1 = g_el[sA1 * NH + hd2];
            lB1 = g_el[sB1 * NH + hd2];
            hA1 = *(const uint4*)((const char*)g_hh + ((long)sA1 * OUT_C + colo) * 2);
            hB1 = *(const uint4*)((const char*)g_hh + ((long)sB1 * OUT_C + colo) * 2);
        }

        // compute iter i (all operands in registers)
        float xA = lA0 + erv; xA = xA >= 0.f ? xA : NEG * xA;
        float xB = lB0 + erv; xB = xB >= 0.f ? xB : NEG * xB;
        float aA = __expf(xA);
        float aB = __expf(xB);
        dsum += aA + aB;

        float2 f;
        f = __half22float2(*(const __half2*)&hA0.x); acc8[0] += f.x * aA; acc8[1] += f.y * aA;
        f = __half22float2(*(const __half2*)&hA0.y); acc8[2] += f.x * aA; acc8[3] += f.y * aA;
        f = __half22float2(*(const __half2*)&hA0.z); acc8[4] += f.x * aA; acc8[5] += f.y * aA;
        f = __half22float2(*(const __half2*)&hA0.w); acc8[6] += f.x * aA; acc8[7] += f.y * aA;
        f = __half22float2(*(const __half2*)&hB0.x); acc8[0] += f.x * aB; acc8[1] += f.y * aB;
        f = __half22float2(*(const __half2*)&hB0.y); acc8[2] += f.x * aB; acc8[3] += f.y * aB;
        f = __half22float2(*(const __half2*)&hB0.z); acc8[4] += f.x * aB; acc8[5] += f.y * aB;
        f = __half22float2(*(const __half2*)&hB0.w); acc8[6] += f.x * aB; acc8[7] += f.y * aB;

        // rotate pipeline
        lA0 = lA1; lB0 = lB1; hA0 = hA1; hB0 = hB1;
        sA1 = sA2; sB1 = sB2;
    }

    // tail: up to 3 edges, parity-split across halves
    for (int e0 = beg + nfull * 4; e0 < end; e0 += 2) {
        int e = e0 + half;
        if (e < end) {
            int s = g_csr_src[e];
            float l = g_el[s * NH + hd2];
            uint4 hv = *(const uint4*)((const char*)g_hh + ((long)s * OUT_C + colo) * 2);
            float x = l + erv; x = x >= 0.f ? x : NEG * x;
            float a = __expf(x);
            dsum += a;
            float2 f;
            f = __half22float2(*(const __half2*)&hv.x); acc8[0] += f.x * a; acc8[1] += f.y * a;
            f = __half22float2(*(const __half2*)&hv.y); acc8[2] += f.x * a; acc8[3] += f.y * a;
            f = __half22float2(*(const __half2*)&hv.z); acc8[4] += f.x * a; acc8[5] += f.y * a;
            f = __half22float2(*(const __half2*)&hv.w); acc8[6] += f.x * a; acc8[7] += f.y * a;
        }
    }

    // merge the two half-warp partial sums (same columns at lane ^ 16)
#pragma unroll
    for (int k = 0; k < 8; k++)
        acc8[k] += __shfl_xor_sync(0xffffffffu, acc8[k], 16);

    // reduce denominator over the 8-lane same-head orbit (4x replication)
    dsum += __shfl_xor_sync(0xffffffffu, dsum, 16);
    dsum += __shfl_xor_sync(0xffffffffu, dsum, 1);
    dsum += __shfl_xor_sync(0xffffffffu, dsum, 2);
    float dn = dsum * 0.25f;
    float rdn = (dn > 0.f) ? (1.0f / dn) : 1.0f;

    if (half == 0) {
        float4 b0 = *(const float4*)(bias + hl * 8);
        float4 b1 = *(const float4*)(bias + hl * 8 + 4);
        float4 o0, o1;
        o0.x = acc8[0] * rdn + b0.x; o0.y = acc8[1] * rdn + b0.y;
        o0.z = acc8[2] * rdn + b0.z; o0.w = acc8[3] * rdn + b0.w;
        o1.x = acc8[4] * rdn + b1.x; o1.y = acc8[5] * rdn + b1.y;
        o1.z = acc8[6] * rdn + b1.z; o1.w = acc8[7] * rdn + b1.w;
        *(float4*)(out + (long)node * OUT_C + hl * 8)     = o0;
        *(float4*)(out + (long)node * OUT_C + hl * 8 + 4) = o1;
    }
}

// ---------------------------------------------------------------------------
// Launch: fork-join so the CSR build (stream s2) overlaps the projection GEMM.
// ---------------------------------------------------------------------------
extern "C" void kernel_launch(void* const* d_in, const int* in_sizes, int n_in,
                              void* d_out, int out_size) {
    const float* feat = (const float*)d_in[0];
    const float* W    = (const float*)d_in[1];
    const float* al   = (const float*)d_in[2];
    const float* ar   = (const float*)d_in[3];
    const float* bias = (const float*)d_in[4];
    const int*   src  = (const int*)d_in[5];
    const int*   dst  = (const int*)d_in[6];
    float* out = (float*)d_out;

    static cudaStream_t s2 = nullptr;
    static cudaEvent_t ev_fork = nullptr, ev_join = nullptr;
    if (s2 == nullptr) {
        cudaStreamCreateWithFlags(&s2, cudaStreamNonBlocking);
        cudaEventCreateWithFlags(&ev_fork, cudaEventDisableTiming);
        cudaEventCreateWithFlags(&ev_join, cudaEventDisableTiming);
    }

    // fork: s2 joins the capture via the event dependency
    cudaEventRecord(ev_fork, 0);
    cudaStreamWaitEvent(s2, ev_fork, 0);

    // branch A (s2): CSR build
    zero_cnt_kernel<<<(NN + 255) / 256, 256, 0, s2>>>();
    hist_kernel<<<(NE / 8 + 255) / 256, 256, 0, s2>>>(dst);
    scan_kernel<<<1, 1024, 0, s2>>>();
    scatter_kernel<<<(NE / 8 + 255) / 256, 256, 0, s2>>>(src, dst);

    // branch B (main stream): projection + logits
    proj_mma_kernel<<<(NN + 127) / 128, 256>>>(feat, W);
    elr_kernel<<<(NN * NH + 255) / 256, 256>>>(al, ar);

    // join
    cudaEventRecord(ev_join, s2);
    cudaStreamWaitEvent(0, ev_join, 0);

    agg_kernel<<<(NN + 7) / 8, 256>>>(bias, out);
}

// round 13
// speedup vs baseline: 1.0060x; 1.0060x over previous
#include <cuda_runtime.h>
#include <cuda_bf16.h>
#include <cuda_fp16.h>
#include <cstdint>

#define NN 50000
#define NE 1600000
#define IN_F 256
#define OUT_C 128   // H*F
#define NH 4
#define NEG 0.2f

// scratch (allocation-free rule: __device__ globals)
__device__ __align__(16) float  g_h[NN * OUT_C];     // projected features fp32 [N,128]
__device__ __align__(16) __half g_hh[NN * OUT_C];    // fp16 copy for gather   [N,128]
__device__ __align__(16) float  g_el[NN * NH];       // left logits  [N,4]
__device__ __align__(16) float  g_er[NN * NH];       // right logits [N,4]
__device__ int g_cnt[NN];                            // in-degree histogram
__device__ int g_off[NN + 1];                        // CSR offsets (by dst)
__device__ __align__(16) int g_rank[NE];             // edge rank within its dst
__device__ int g_csr_src[NE];                        // src node per CSR slot

// ---------------------------------------------------------------------------
// CSR build: zero -> hist(+rank) -> scan -> scatter (atomic-free scatter)
// NE % 8 == 0: one guard per thread, int4-vectorized edge loads.
// ---------------------------------------------------------------------------
__global__ void zero_cnt_kernel() {
    int i = blockIdx.x * blockDim.x + threadIdx.x;
    if (i < NN) g_cnt[i] = 0;
}

__global__ void hist_kernel(const int* __restrict__ dst) {
    int base = (blockIdx.x * blockDim.x + threadIdx.x) * 8;
    if (base >= NE) return;
    int4 d0 = *(const int4*)(dst + base);
    int4 d1 = *(const int4*)(dst + base + 4);
    int d[8] = {d0.x, d0.y, d0.z, d0.w, d1.x, d1.y, d1.z, d1.w};
    int r[8];
#pragma unroll
    for (int j = 0; j < 8; j++) r[j] = atomicAdd(&g_cnt[d[j]], 1);
    *(int4*)(g_rank + base)     = make_int4(r[0], r[1], r[2], r[3]);
    *(int4*)(g_rank + base + 4) = make_int4(r[4], r[5], r[6], r[7]);
}

__global__ __launch_bounds__(1024) void scan_kernel() {
    __shared__ int ssum[1024];
    const int CH = (NN + 1023) / 1024;  // 49
    int t = threadIdx.x;
    int b = t * CH;
    int e = min(b + CH, NN);
    int s = 0;
    for (int i = b; i < e; i++) s += g_cnt[i];
    ssum[t] = s;
    __syncthreads();
    for (int off = 1; off < 1024; off <<= 1) {
        int v = (t >= off) ? ssum[t - off] : 0;
        __syncthreads();
        ssum[t] += v;
        __syncthreads();
    }
    int run = ssum[t] - s;
    for (int i = b; i < e; i++) {
        int c = g_cnt[i];
        g_off[i] = run;
        run += c;
    }
    if (t == 1023) g_off[NN] = NE;
}

__global__ void scatter_kernel(const int* __restrict__ src, const int* __restrict__ dst) {
    int base = (blockIdx.x * blockDim.x + threadIdx.x) * 8;
    if (base >= NE) return;
    int4 d0 = *(const int4*)(dst + base);
    int4 d1 = *(const int4*)(dst + base + 4);
    int4 s0 = *(const int4*)(src + base);
    int4 s1 = *(const int4*)(src + base + 4);
    int4 r0 = *(const int4*)(g_rank + base);
    int4 r1 = *(const int4*)(g_rank + base + 4);
    int d[8] = {d0.x, d0.y, d0.z, d0.w, d1.x, d1.y, d1.z, d1.w};
    int s[8] = {s0.x, s0.y, s0.z, s0.w, s1.x, s1.y, s1.z, s1.w};
    int r[8] = {r0.x, r0.y, r0.z, r0.w, r1.x, r1.y, r1.z, r1.w};
    int o[8];
#pragma unroll
    for (int j = 0; j < 8; j++) o[j] = g_off[d[j]];
#pragma unroll
    for (int j = 0; j < 8; j++) g_csr_src[o[j] + r[j]] = s[j];
}

// ---------------------------------------------------------------------------
// Projection: h = feat @ W^T via bf16-split tensor-core GEMM.
// ---------------------------------------------------------------------------
#define SPIT 40

__device__ __forceinline__ void bsplit(float x, __nv_bfloat16& hi, __nv_bfloat16& lo) {
    hi = __float2bfloat16_rn(x);
    lo = __float2bfloat16_rn(x - __bfloat162float(hi));
}

__device__ __forceinline__ void ldm_x4(unsigned* r, const __nv_bfloat16* p) {
    unsigned a = (unsigned)__cvta_generic_to_shared(p);
    asm volatile("ldmatrix.sync.aligned.m8n8.x4.shared.b16 {%0,%1,%2,%3}, [%4];"
                 : "=r"(r[0]), "=r"(r[1]), "=r"(r[2]), "=r"(r[3]) : "r"(a));
}

__device__ __forceinline__ void mma16816(float* c, const unsigned* a,
                                         unsigned b0, unsigned b1) {
    asm volatile("mma.sync.aligned.m16n8k16.row.col.f32.bf16.bf16.f32 "
                 "{%0,%1,%2,%3},{%4,%5,%6,%7},{%8,%9},{%0,%1,%2,%3};"
                 : "+f"(c[0]), "+f"(c[1]), "+f"(c[2]), "+f"(c[3])
                 : "r"(a[0]), "r"(a[1]), "r"(a[2]), "r"(a[3]), "r"(b0), "r"(b1));
}

__global__ __launch_bounds__(256) void proj_mma_kernel(
    const float* __restrict__ feat, const float* __restrict__ W)
{
    __shared__ __nv_bfloat16 sAhi[128][SPIT];
    __shared__ __nv_bfloat16 sAlo[128][SPIT];
    __shared__ __nv_bfloat16 sBhi[128][SPIT];
    __shared__ __nv_bfloat16 sBlo[128][SPIT];

    int t = threadIdx.x;
    int lane = t & 31;
    int wid = t >> 5;
    int wm = wid & 3;
    int wn = wid >> 2;
    int node0 = blockIdx.x * 128;

    float acc[2][8][4];
#pragma unroll
    for (int i = 0; i < 2; i++)
#pragma unroll
        for (int j = 0; j < 8; j++)
#pragma unroll
            for (int q = 0; q < 4; q++) acc[i][j][q] = 0.0f;

    for (int k0 = 0; k0 < IN_F; k0 += 32) {
#pragma unroll
        for (int j = 0; j < 4; j++) {
            int id = t + j * 256;            // 0..1023
            int row = id >> 3;
            int c4 = (id & 7) * 4;
            int node = node0 + row;
            if (node >= NN) node = NN - 1;
            float4 v = *(const float4*)(feat + (long)node * IN_F + k0 + c4);
            bsplit(v.x, sAhi[row][c4 + 0], sAlo[row][c4 + 0]);
            bsplit(v.y, sAhi[row][c4 + 1], sAlo[row][c4 + 1]);
            bsplit(v.z, sAhi[row][c4 + 2], sAlo[row][c4 + 2]);
            bsplit(v.w, sAhi[row][c4 + 3], sAlo[row][c4 + 3]);
        }
#pragma unroll
        for (int j = 0; j < 4; j++) {
            int id = t + j * 256;
            int row = id >> 3;
            int c4 = (id & 7) * 4;
            float4 v = *(const float4*)(W + (long)row * IN_F + k0 + c4);
            bsplit(v.x, sBhi[row][c4 + 0], sBlo[row][c4 + 0]);
            bsplit(v.y, sBhi[row][c4 + 1], sBlo[row][c4 + 1]);
            bsplit(v.z, sBhi[row][c4 + 2], sBlo[row][c4 + 2]);
            bsplit(v.w, sBhi[row][c4 + 3], sBlo[row][c4 + 3]);
        }
        __syncthreads();

#pragma unroll
        for (int ks = 0; ks < 2; ks++) {
            int koff = ks * 16;
            unsigned ahi[2][4], alo[2][4];
#pragma unroll
            for (int mt = 0; mt < 2; mt++) {
                int row = wm * 32 + mt * 16 + (lane & 15);
                int col = koff + (lane >> 4) * 8;
                ldm_x4(ahi[mt], &sAhi[row][col]);
                ldm_x4(alo[mt], &sAlo[row][col]);
            }
            unsigned bhi[4][4], blo[4][4];
#pragma unroll
            for (int ng = 0; ng < 4; ng++) {
                int row = wn * 64 + ng * 16 + (lane & 7) + ((lane >> 4) << 3);
                int col = koff + ((lane >> 3) & 1) * 8;
                ldm_x4(bhi[ng], &sBhi[row][col]);
                ldm_x4(blo[ng], &sBlo[row][col]);
            }
#pragma unroll
            for (int mt = 0; mt < 2; mt++)
#pragma unroll
                for (int ng = 0; ng < 4; ng++)
#pragma unroll
                    for (int hf = 0; hf < 2; hf++) {
                        float* c = acc[mt][ng * 2 + hf];
                        mma16816(c, ahi[mt], bhi[ng][hf * 2], bhi[ng][hf * 2 + 1]);
                        mma16816(c, ahi[mt], blo[ng][hf * 2], blo[ng][hf * 2 + 1]);
                        mma16816(c, alo[mt], bhi[ng][hf * 2], bhi[ng][hf * 2 + 1]);
                    }
        }
        __syncthreads();
    }

    // epilogue: C fragment -> g_h (fp32) + g_hh (fp16)
    int grp = lane >> 2;
    int tg = lane & 3;
#pragma unroll
    for (int mt = 0; mt < 2; mt++) {
#pragma unroll
        for (int nt = 0; nt < 8; nt++) {
            int row = node0 + wm * 32 + mt * 16 + grp;
            int col = wn * 64 + nt * 8 + tg * 2;
            float* c = acc[mt][nt];
            if (row < NN) {
                *(float2*)(g_h + (long)row * OUT_C + col) = make_float2(c[0], c[1]);
                *(__half2*)(g_hh + (long)row * OUT_C + col) = __floats2half2_rn(c[0], c[1]);
            }
            if (row + 8 < NN) {
                *(float2*)(g_h + (long)(row + 8) * OUT_C + col) = make_float2(c[2], c[3]);
                *(__half2*)(g_hh + (long)(row + 8) * OUT_C + col) = __floats2half2_rn(c[2], c[3]);
            }
        }
    }
}

// ---------------------------------------------------------------------------
// el/er: per (node, head) dot of h row-chunk with attn vectors (L2-resident)
// ---------------------------------------------------------------------------
__global__ void elr_kernel(const float* __restrict__ al, const float* __restrict__ ar) {
    int i = blockIdx.x * blockDim.x + threadIdx.x;   // node*NH + head
    if (i >= NN * NH) return;
    int node = i >> 2;
    int head = i & 3;
    const float* hp = g_h + (long)node * OUT_C + head * 32;
    float sl = 0.f, sr = 0.f;
#pragma unroll
    for (int j = 0; j < 8; j++) {
        float4 v = *(const float4*)(hp + j * 4);
        float4 a = *(const float4*)(al + head * 32 + j * 4);
        float4 b = *(const float4*)(ar + head * 32 + j * 4);
        sl += v.x * a.x + v.y * a.y + v.z * a.z + v.w * a.w;
        sr += v.x * b.x + v.y * b.y + v.z * b.z + v.w * b.w;
    }
    g_el[i] = sl;
    g_er[i] = sr;
}

// ---------------------------------------------------------------------------
// Fused softmax + aggregation: single-phase, half-warp per edge (R11 layout),
// all gather loads via the read-only (ld.global.nc) path: g_hh rows have ~32x
// reuse (12.8 MB unique vs 410 MB gathered) -> L1 captures part of it.
// ---------------------------------------------------------------------------
__global__ __launch_bounds__(256) void agg_kernel(const float* __restrict__ bias,
                                                  float* __restrict__ out)
{
    int wib  = threadIdx.x >> 5;
    int lane = threadIdx.x & 31;
    int node = blockIdx.x * 8 + wib;
    if (node >= NN) return;

    int beg = g_off[node];
    int end = g_off[node + 1];

    int half = lane >> 4;      // which edge of the pair
    int hl   = lane & 15;      // lane within half-warp
    int hd2  = hl >> 2;        // head for my column range

    const float erv = g_er[node * NH + hd2];

    float dsum = 0.f;
    float acc8[8];
#pragma unroll
    for (int k = 0; k < 8; k++) acc8[k] = 0.f;

    const long colo = (long)hl * 8;   // fp16 column offset for this lane

    int e0 = beg;
    // main loop: 4 edges per warp iteration (2 per half-warp); unroll 2 gives
    // the scheduler two independent groups (8 edges in flight) without the
    // register cost of manual pipelining.
#pragma unroll 2
    for (; e0 + 3 < end; e0 += 4) {
        int eA = e0 + half * 2;
        int sA = __ldg(&g_csr_src[eA]);
        int sB = __ldg(&g_csr_src[eA + 1]);
        float lA = __ldg(&g_el[sA * NH + hd2]);
        float lB = __ldg(&g_el[sB * NH + hd2]);
        uint4 hA = __ldg((const uint4*)((const char*)g_hh + ((long)sA * OUT_C + colo) * 2));
        uint4 hB = __ldg((const uint4*)((const char*)g_hh + ((long)sB * OUT_C + colo) * 2));

        float xA = lA + erv; xA = xA >= 0.f ? xA : NEG * xA;
        float xB = lB + erv; xB = xB >= 0.f ? xB : NEG * xB;
        float aA = __expf(xA);
        float aB = __expf(xB);
        dsum += aA + aB;

        float2 f;
        f = __half22float2(*(const __half2*)&hA.x); acc8[0] += f.x * aA; acc8[1] += f.y * aA;
        f = __half22float2(*(const __half2*)&hA.y); acc8[2] += f.x * aA; acc8[3] += f.y * aA;
        f = __half22float2(*(const __half2*)&hA.z); acc8[4] += f.x * aA; acc8[5] += f.y * aA;
        f = __half22float2(*(const __half2*)&hA.w); acc8[6] += f.x * aA; acc8[7] += f.y * aA;
        f = __half22float2(*(const __half2*)&hB.x); acc8[0] += f.x * aB; acc8[1] += f.y * aB;
        f = __half22float2(*(const __half2*)&hB.y); acc8[2] += f.x * aB; acc8[3] += f.y * aB;
        f = __half22float2(*(const __half2*)&hB.z); acc8[4] += f.x * aB; acc8[5] += f.y * aB;
        f = __half22float2(*(const __half2*)&hB.w); acc8[6] += f.x * aB; acc8[7] += f.y * aB;
    }
    // tail: up to 3 edges, parity-split across halves
    for (; e0 < end; e0 += 2) {
        int e = e0 + half;
        if (e < end) {
            int s = __ldg(&g_csr_src[e]);
            float l = __ldg(&g_el[s * NH + hd2]);
            uint4 hv = __ldg((const uint4*)((const char*)g_hh + ((long)s * OUT_C + colo) * 2));
            float x = l + erv; x = x >= 0.f ? x : NEG * x;
            float a = __expf(x);
            dsum += a;
            float2 f;
            f = __half22float2(*(const __half2*)&hv.x); acc8[0] += f.x * a; acc8[1] += f.y * a;
            f = __half22float2(*(const __half2*)&hv.y); acc8[2] += f.x * a; acc8[3] += f.y * a;
            f = __half22float2(*(const __half2*)&hv.z); acc8[4] += f.x * a; acc8[5] += f.y * a;
            f = __half22float2(*(const __half2*)&hv.w); acc8[6] += f.x * a; acc8[7] += f.y * a;
        }
    }

    // merge the two half-warp partial sums (same columns at lane ^ 16)
#pragma unroll
    for (int k = 0; k < 8; k++)
        acc8[k] += __shfl_xor_sync(0xffffffffu, acc8[k], 16);

    // reduce denominator over the 8-lane same-head orbit (4x replication)
    dsum += __shfl_xor_sync(0xffffffffu, dsum, 16);
    dsum += __shfl_xor_sync(0xffffffffu, dsum, 1);
    dsum += __shfl_xor_sync(0xffffffffu, dsum, 2);
    float dn = dsum * 0.25f;
    float rdn = (dn > 0.f) ? (1.0f / dn) : 1.0f;

    if (half == 0) {
        float4 b0 = *(const float4*)(bias + hl * 8);
        float4 b1 = *(const float4*)(bias + hl * 8 + 4);
        float4 o0, o1;
        o0.x = acc8[0] * rdn + b0.x; o0.y = acc8[1] * rdn + b0.y;
        o0.z = acc8[2] * rdn + b0.z; o0.w = acc8[3] * rdn + b0.w;
        o1.x = acc8[4] * rdn + b1.x; o1.y = acc8[5] * rdn + b1.y;
        o1.z = acc8[6] * rdn + b1.z; o1.w = acc8[7] * rdn + b1.w;
        *(float4*)(out + (long)node * OUT_C + hl * 8)     = o0;
        *(float4*)(out + (long)node * OUT_C + hl * 8 + 4) = o1;
    }
}

// ---------------------------------------------------------------------------
// Launch: fork-join so the CSR build (stream s2) overlaps the projection GEMM.
// ---------------------------------------------------------------------------
extern "C" void kernel_launch(void* const* d_in, const int* in_sizes, int n_in,
                              void* d_out, int out_size) {
    const float* feat = (const float*)d_in[0];
    const float* W    = (const float*)d_in[1];
    const float* al   = (const float*)d_in[2];
    const float* ar   = (const float*)d_in[3];
    const float* bias = (const float*)d_in[4];
    const int*   src  = (const int*)d_in[5];
    const int*   dst  = (const int*)d_in[6];
    float* out = (float*)d_out;

    static cudaStream_t s2 = nullptr;
    static cudaEvent_t ev_fork = nullptr, ev_join = nullptr;
    if (s2 == nullptr) {
        cudaStreamCreateWithFlags(&s2, cudaStreamNonBlocking);
        cudaEventCreateWithFlags(&ev_fork, cudaEventDisableTiming);
        cudaEventCreateWithFlags(&ev_join, cudaEventDisableTiming);
    }

    // fork: s2 joins the capture via the event dependency
    cudaEventRecord(ev_fork, 0);
    cudaStreamWaitEvent(s2, ev_fork, 0);

    // branch A (s2): CSR build
    zero_cnt_kernel<<<(NN + 255) / 256, 256, 0, s2>>>();
    hist_kernel<<<(NE / 8 + 255) / 256, 256, 0, s2>>>(dst);
    scan_kernel<<<1, 1024, 0, s2>>>();
    scatter_kernel<<<(NE / 8 + 255) / 256, 256, 0, s2>>>(src, dst);

    // branch B (main stream): projection + logits
    proj_mma_kernel<<<(NN + 127) / 128, 256>>>(feat, W);
    elr_kernel<<<(NN * NH + 255) / 256, 256>>>(al, ar);

    // join
    cudaEventRecord(ev_join, s2);
    cudaStreamWaitEvent(0, ev_join, 0);

    agg_kernel<<<(NN + 7) / 8, 256>>>(bias, out);
}

// round 14
// speedup vs baseline: 1.3114x; 1.3036x over previous
#include <cuda_runtime.h>
#include <cuda_bf16.h>
#include <cuda_fp16.h>
#include <cstdint>

#define NN 50000
#define NE 1600000
#define IN_F 256
#define OUT_C 128   // H*F
#define NH 4
#define NEG 0.2f

// scratch (allocation-free rule: __device__ globals)
__device__ __align__(16) float  g_h[NN * OUT_C];     // projected features fp32 [N,128]
__device__ __align__(16) __half g_hh[NN * OUT_C];    // fp16 copy for gather   [N,128]
__device__ __align__(16) float  g_el[NN * NH];       // left logits  [N,4]
__device__ __align__(16) float  g_er[NN * NH];       // right logits [N,4]
__device__ int g_cnt[NN];                            // in-degree histogram
__device__ int g_off[NN + 1];                        // CSR offsets (by dst)
__device__ int g_bsum[64];                           // per-block scan sums
__device__ __align__(16) int g_rank[NE];             // edge rank within its dst
__device__ int g_csr_src[NE];                        // src node per CSR slot

// ---------------------------------------------------------------------------
// CSR build: zero -> hist(+rank) -> 3-phase multi-block scan -> scatter
// ---------------------------------------------------------------------------
__global__ void zero_cnt_kernel() {
    int i = blockIdx.x * blockDim.x + threadIdx.x;
    if (i < NN) g_cnt[i] = 0;
}

__global__ void hist_kernel(const int* __restrict__ dst) {
    int base = (blockIdx.x * blockDim.x + threadIdx.x) * 8;
    if (base >= NE) return;
    int4 d0 = *(const int4*)(dst + base);
    int4 d1 = *(const int4*)(dst + base + 4);
    int d[8] = {d0.x, d0.y, d0.z, d0.w, d1.x, d1.y, d1.z, d1.w};
    int r[8];
#pragma unroll
    for (int j = 0; j < 8; j++) r[j] = atomicAdd(&g_cnt[d[j]], 1);
    *(int4*)(g_rank + base)     = make_int4(r[0], r[1], r[2], r[3]);
    *(int4*)(g_rank + base + 4) = make_int4(r[4], r[5], r[6], r[7]);
}

// phase 1: per-block exclusive scan of 1024 counts + block totals (49 blocks)
__global__ __launch_bounds__(1024) void scan1_kernel() {
    __shared__ int ssum[1024];
    int b = blockIdx.x, t = threadIdx.x;
    int i = b * 1024 + t;
    int c = (i < NN) ? g_cnt[i] : 0;
    ssum[t] = c;
    __syncthreads();
    for (int off = 1; off < 1024; off <<= 1) {
        int v = (t >= off) ? ssum[t - off] : 0;
        __syncthreads();
        ssum[t] += v;
        __syncthreads();
    }
    if (i <= NN) g_off[i] = ssum[t] - c;   // block-local exclusive prefix
    if (t == 1023) g_bsum[b] = ssum[1023];
}

// phase 2: exclusive scan of the 49 block sums (in place)
__global__ void scan2_kernel() {
    __shared__ int s[64];
    int t = threadIdx.x;
    int v = (t < 49) ? g_bsum[t] : 0;
    s[t] = v;
    __syncthreads();
    for (int off = 1; off < 64; off <<= 1) {
        int u = (t >= off) ? s[t - off] : 0;
        __syncthreads();
        s[t] += u;
        __syncthreads();
    }
    if (t < 49) g_bsum[t] = s[t] - v;
}

// phase 3: add block offsets (49 blocks)
__global__ __launch_bounds__(1024) void scan3_kernel() {
    int b = blockIdx.x, t = threadIdx.x;
    int i = b * 1024 + t;
    if (i <= NN) g_off[i] += g_bsum[b];
}

__global__ void scatter_kernel(const int* __restrict__ src, const int* __restrict__ dst) {
    int base = (blockIdx.x * blockDim.x + threadIdx.x) * 8;
    if (base >= NE) return;
    int4 d0 = *(const int4*)(dst + base);
    int4 d1 = *(const int4*)(dst + base + 4);
    int4 s0 = *(const int4*)(src + base);
    int4 s1 = *(const int4*)(src + base + 4);
    int4 r0 = *(const int4*)(g_rank + base);
    int4 r1 = *(const int4*)(g_rank + base + 4);
    int d[8] = {d0.x, d0.y, d0.z, d0.w, d1.x, d1.y, d1.z, d1.w};
    int s[8] = {s0.x, s0.y, s0.z, s0.w, s1.x, s1.y, s1.z, s1.w};
    int r[8] = {r0.x, r0.y, r0.z, r0.w, r1.x, r1.y, r1.z, r1.w};
    int o[8];
#pragma unroll
    for (int j = 0; j < 8; j++) o[j] = g_off[d[j]];
#pragma unroll
    for (int j = 0; j < 8; j++) g_csr_src[o[j] + r[j]] = s[j];
}

// ---------------------------------------------------------------------------
// Projection: h = feat @ W^T via bf16-split tensor-core GEMM.
// ---------------------------------------------------------------------------
#define SPIT 40

__device__ __forceinline__ void bsplit(float x, __nv_bfloat16& hi, __nv_bfloat16& lo) {
    hi = __float2bfloat16_rn(x);
    lo = __float2bfloat16_rn(x - __bfloat162float(hi));
}

__device__ __forceinline__ void ldm_x4(unsigned* r, const __nv_bfloat16* p) {
    unsigned a = (unsigned)__cvta_generic_to_shared(p);
    asm volatile("ldmatrix.sync.aligned.m8n8.x4.shared.b16 {%0,%1,%2,%3}, [%4];"
                 : "=r"(r[0]), "=r"(r[1]), "=r"(r[2]), "=r"(r[3]) : "r"(a));
}

__device__ __forceinline__ void mma16816(float* c, const unsigned* a,
                                         unsigned b0, unsigned b1) {
    asm volatile("mma.sync.aligned.m16n8k16.row.col.f32.bf16.bf16.f32 "
                 "{%0,%1,%2,%3},{%4,%5,%6,%7},{%8,%9},{%0,%1,%2,%3};"
                 : "+f"(c[0]), "+f"(c[1]), "+f"(c[2]), "+f"(c[3])
                 : "r"(a[0]), "r"(a[1]), "r"(a[2]), "r"(a[3]), "r"(b0), "r"(b1));
}

__global__ __launch_bounds__(256) void proj_mma_kernel(
    const float* __restrict__ feat, const float* __restrict__ W)
{
    __shared__ __nv_bfloat16 sAhi[128][SPIT];
    __shared__ __nv_bfloat16 sAlo[128][SPIT];
    __shared__ __nv_bfloat16 sBhi[128][SPIT];
    __shared__ __nv_bfloat16 sBlo[128][SPIT];

    int t = threadIdx.x;
    int lane = t & 31;
    int wid = t >> 5;
    int wm = wid & 3;
    int wn = wid >> 2;
    int node0 = blockIdx.x * 128;

    float acc[2][8][4];
#pragma unroll
    for (int i = 0; i < 2; i++)
#pragma unroll
        for (int j = 0; j < 8; j++)
#pragma unroll
            for (int q = 0; q < 4; q++) acc[i][j][q] = 0.0f;

    for (int k0 = 0; k0 < IN_F; k0 += 32) {
#pragma unroll
        for (int j = 0; j < 4; j++) {
            int id = t + j * 256;            // 0..1023
            int row = id >> 3;
            int c4 = (id & 7) * 4;
            int node = node0 + row;
            if (node >= NN) node = NN - 1;
            float4 v = *(const float4*)(feat + (long)node * IN_F + k0 + c4);
            bsplit(v.x, sAhi[row][c4 + 0], sAlo[row][c4 + 0]);
            bsplit(v.y, sAhi[row][c4 + 1], sAlo[row][c4 + 1]);
            bsplit(v.z, sAhi[row][c4 + 2], sAlo[row][c4 + 2]);
            bsplit(v.w, sAhi[row][c4 + 3], sAlo[row][c4 + 3]);
        }
#pragma unroll
        for (int j = 0; j < 4; j++) {
            int id = t + j * 256;
            int row = id >> 3;
            int c4 = (id & 7) * 4;
            float4 v = *(const float4*)(W + (long)row * IN_F + k0 + c4);
            bsplit(v.x, sBhi[row][c4 + 0], sBlo[row][c4 + 0]);
            bsplit(v.y, sBhi[row][c4 + 1], sBlo[row][c4 + 1]);
            bsplit(v.z, sBhi[row][c4 + 2], sBlo[row][c4 + 2]);
            bsplit(v.w, sBhi[row][c4 + 3], sBlo[row][c4 + 3]);
        }
        __syncthreads();

#pragma unroll
        for (int ks = 0; ks < 2; ks++) {
            int koff = ks * 16;
            unsigned ahi[2][4], alo[2][4];
#pragma unroll
            for (int mt = 0; mt < 2; mt++) {
                int row = wm * 32 + mt * 16 + (lane & 15);
                int col = koff + (lane >> 4) * 8;
                ldm_x4(ahi[mt], &sAhi[row][col]);
                ldm_x4(alo[mt], &sAlo[row][col]);
            }
            unsigned bhi[4][4], blo[4][4];
#pragma unroll
            for (int ng = 0; ng < 4; ng++) {
                int row = wn * 64 + ng * 16 + (lane & 7) + ((lane >> 4) << 3);
                int col = koff + ((lane >> 3) & 1) * 8;
                ldm_x4(bhi[ng], &sBhi[row][col]);
                ldm_x4(blo[ng], &sBlo[row][col]);
            }
#pragma unroll
            for (int mt = 0; mt < 2; mt++)
#pragma unroll
                for (int ng = 0; ng < 4; ng++)
#pragma unroll
                    for (int hf = 0; hf < 2; hf++) {
                        float* c = acc[mt][ng * 2 + hf];
                        mma16816(c, ahi[mt], bhi[ng][hf * 2], bhi[ng][hf * 2 + 1]);
                        mma16816(c, ahi[mt], blo[ng][hf * 2], blo[ng][hf * 2 + 1]);
                        mma16816(c, alo[mt], bhi[ng][hf * 2], bhi[ng][hf * 2 + 1]);
                    }
        }
        __syncthreads();
    }

    // epilogue: C fragment -> g_h (fp32) + g_hh (fp16)
    int grp = lane >> 2;
    int tg = lane & 3;
#pragma unroll
    for (int mt = 0; mt < 2; mt++) {
#pragma unroll
        for (int nt = 0; nt < 8; nt++) {
            int row = node0 + wm * 32 + mt * 16 + grp;
            int col = wn * 64 + nt * 8 + tg * 2;
            float* c = acc[mt][nt];
            if (row < NN) {
                *(float2*)(g_h + (long)row * OUT_C + col) = make_float2(c[0], c[1]);
                *(__half2*)(g_hh + (long)row * OUT_C + col) = __floats2half2_rn(c[0], c[1]);
            }
            if (row + 8 < NN) {
                *(float2*)(g_h + (long)(row + 8) * OUT_C + col) = make_float2(c[2], c[3]);
                *(__half2*)(g_hh + (long)(row + 8) * OUT_C + col) = __floats2half2_rn(c[2], c[3]);
            }
        }
    }
}

// ---------------------------------------------------------------------------
// el/er: per (node, head) dot of h row-chunk with attn vectors (L2-resident)
// ---------------------------------------------------------------------------
__global__ void elr_kernel(const float* __restrict__ al, const float* __restrict__ ar) {
    int i = blockIdx.x * blockDim.x + threadIdx.x;   // node*NH + head
    if (i >= NN * NH) return;
    int node = i >> 2;
    int head = i & 3;
    const float* hp = g_h + (long)node * OUT_C + head * 32;
    float sl = 0.f, sr = 0.f;
#pragma unroll
    for (int j = 0; j < 8; j++) {
        float4 v = *(const float4*)(hp + j * 4);
        float4 a = *(const float4*)(al + head * 32 + j * 4);
        float4 b = *(const float4*)(ar + head * 32 + j * 4);
        sl += v.x * a.x + v.y * a.y + v.z * a.z + v.w * a.w;
        sr += v.x * b.x + v.y * b.y + v.z * b.z + v.w * b.w;
    }
    g_el[i] = sl;
    g_er[i] = sr;
}

// ---------------------------------------------------------------------------
// Fused softmax + aggregation: single-phase, half-warp per edge (R11, verified
// best). Flat loop; compiler schedules the loads fine.
// ---------------------------------------------------------------------------
__global__ __launch_bounds__(256) void agg_kernel(const float* __restrict__ bias,
                                                  float* __restrict__ out)
{
    int wib  = threadIdx.x >> 5;
    int lane = threadIdx.x & 31;
    int node = blockIdx.x * 8 + wib;
    if (node >= NN) return;

    int beg = g_off[node];
    int end = g_off[node + 1];

    int half = lane >> 4;      // which edge of the pair
    int hl   = lane & 15;      // lane within half-warp
    int hd2  = hl >> 2;        // head for my column range

    const float erv = g_er[node * NH + hd2];

    float dsum = 0.f;
    float acc8[8];
#pragma unroll
    for (int k = 0; k < 8; k++) acc8[k] = 0.f;

    const long colo = (long)hl * 8;   // fp16 column offset for this lane

    int e0 = beg;
    // main loop: 4 edges per warp iteration (2 per half-warp)
    for (; e0 + 3 < end; e0 += 4) {
        int eA = e0 + half * 2;
        int sA = g_csr_src[eA];
        int sB = g_csr_src[eA + 1];
        float lA = g_el[sA * NH + hd2];
        float lB = g_el[sB * NH + hd2];
        uint4 hA = *(const uint4*)((const char*)g_hh + ((long)sA * OUT_C + colo) * 2);
        uint4 hB = *(const uint4*)((const char*)g_hh + ((long)sB * OUT_C + colo) * 2);

        float xA = lA + erv; xA = xA >= 0.f ? xA : NEG * xA;
        float xB = lB + erv; xB = xB >= 0.f ? xB : NEG * xB;
        float aA = __expf(xA);
        float aB = __expf(xB);
        dsum += aA + aB;

        float2 f;
        f = __half22float2(*(const __half2*)&hA.x); acc8[0] += f.x * aA; acc8[1] += f.y * aA;
        f = __half22float2(*(const __half2*)&hA.y); acc8[2] += f.x * aA; acc8[3] += f.y * aA;
        f = __half22float2(*(const __half2*)&hA.z); acc8[4] += f.x * aA; acc8[5] += f.y * aA;
        f = __half22float2(*(const __half2*)&hA.w); acc8[6] += f.x * aA; acc8[7] += f.y * aA;
        f = __half22float2(*(const __half2*)&hB.x); acc8[0] += f.x * aB; acc8[1] += f.y * aB;
        f = __half22float2(*(const __half2*)&hB.y); acc8[2] += f.x * aB; acc8[3] += f.y * aB;
        f = __half22float2(*(const __half2*)&hB.z); acc8[4] += f.x * aB; acc8[5] += f.y * aB;
        f = __half22float2(*(const __half2*)&hB.w); acc8[6] += f.x * aB; acc8[7] += f.y * aB;
    }
    // tail: up to 3 edges, parity-split across halves
    for (; e0 < end; e0 += 2) {
        int e = e0 + half;
        if (e < end) {
            int s = g_csr_src[e];
            float l = g_el[s * NH + hd2];
            uint4 hv = *(const uint4*)((const char*)g_hh + ((long)s * OUT_C + colo) * 2);
            float x = l + erv; x = x >= 0.f ? x : NEG * x;
            float a = __expf(x);
            dsum += a;
            float2 f;
            f = __half22float2(*(const __half2*)&hv.x); acc8[0] += f.x * a; acc8[1] += f.y * a;
            f = __half22float2(*(const __half2*)&hv.y); acc8[2] += f.x * a; acc8[3] += f.y * a;
            f = __half22float2(*(const __half2*)&hv.z); acc8[4] += f.x * a; acc8[5] += f.y * a;
            f = __half22float2(*(const __half2*)&hv.w); acc8[6] += f.x * a; acc8[7] += f.y * a;
        }
    }

    // merge the two half-warp partial sums (same columns at lane ^ 16)
#pragma unroll
    for (int k = 0; k < 8; k++)
        acc8[k] += __shfl_xor_sync(0xffffffffu, acc8[k], 16);

    // reduce denominator over the 8-lane same-head orbit (4x replication)
    dsum += __shfl_xor_sync(0xffffffffu, dsum, 16);
    dsum += __shfl_xor_sync(0xffffffffu, dsum, 1);
    dsum += __shfl_xor_sync(0xffffffffu, dsum, 2);
    float dn = dsum * 0.25f;
    float rdn = (dn > 0.f) ? (1.0f / dn) : 1.0f;

    if (half == 0) {
        float4 b0 = *(const float4*)(bias + hl * 8);
        float4 b1 = *(const float4*)(bias + hl * 8 + 4);
        float4 o0, o1;
        o0.x = acc8[0] * rdn + b0.x; o0.y = acc8[1] * rdn + b0.y;
        o0.z = acc8[2] * rdn + b0.z; o0.w = acc8[3] * rdn + b0.w;
        o1.x = acc8[4] * rdn + b1.x; o1.y = acc8[5] * rdn + b1.y;
        o1.z = acc8[6] * rdn + b1.z; o1.w = acc8[7] * rdn + b1.w;
        *(float4*)(out + (long)node * OUT_C + hl * 8)     = o0;
        *(float4*)(out + (long)node * OUT_C + hl * 8 + 4) = o1;
    }
}

// ---------------------------------------------------------------------------
// Launch: fork-join so the CSR build (stream s2) overlaps the projection GEMM.
// ---------------------------------------------------------------------------
extern "C" void kernel_launch(void* const* d_in, const int* in_sizes, int n_in,
                              void* d_out, int out_size) {
    const float* feat = (const float*)d_in[0];
    const float* W    = (const float*)d_in[1];
    const float* al   = (const float*)d_in[2];
    const float* ar   = (const float*)d_in[3];
    const float* bias = (const float*)d_in[4];
    const int*   src  = (const int*)d_in[5];
    const int*   dst  = (const int*)d_in[6];
    float* out = (float*)d_out;

    static cudaStream_t s2 = nullptr;
    static cudaEvent_t ev_fork = nullptr, ev_join = nullptr;
    if (s2 == nullptr) {
        cudaStreamCreateWithFlags(&s2, cudaStreamNonBlocking);
        cudaEventCreateWithFlags(&ev_fork, cudaEventDisableTiming);
        cudaEventCreateWithFlags(&ev_join, cudaEventDisableTiming);
    }

    // fork: s2 joins the capture via the event dependency
    cudaEventRecord(ev_fork, 0);
    cudaStreamWaitEvent(s2, ev_fork, 0);

    // branch A (s2): CSR build
    zero_cnt_kernel<<<(NN + 255) / 256, 256, 0, s2>>>();
    hist_kernel<<<(NE / 8 + 255) / 256, 256, 0, s2>>>(dst);
    scan1_kernel<<<49, 1024, 0, s2>>>();
    scan2_kernel<<<1, 64, 0, s2>>>();
    scan3_kernel<<<49, 1024, 0, s2>>>();
    scatter_kernel<<<(NE / 8 + 255) / 256, 256, 0, s2>>>(src, dst);

    // branch B (main stream): projection + logits
    proj_mma_kernel<<<(NN + 127) / 128, 256>>>(feat, W);
    elr_kernel<<<(NN * NH + 255) / 256, 256>>>(al, ar);

    // join
    cudaEventRecord(ev_join, s2);
    cudaStreamWaitEvent(0, ev_join, 0);

    agg_kernel<<<(NN + 7) / 8, 256>>>(bias, out);
}